// round 16
// baseline (speedup 1.0000x reference)
#include <cuda_runtime.h>
#include <cuda_fp16.h>
#include <cstdint>
#include <math.h>

// SwapV2 dense via mma.sync.m16n8k16 (fp16 in, f32 acc). B=8, C=32, H=W=64.
// R16: warp = 16-px strip x 32 channels -> 4 independent MMA chains per warp
// (was 2), A-frags 16 regs (was 32). 512 thr/CTA, 128 CTAs = one wave.

#define HWP 4096
#define SW(o) ((o) ^ (((o) >> 3) & 0x70))

#define SM_A   0                          // 256 rows x 128B (wx fp16 swz)
#define SM_B   32768                      // 2 x 256 rows x 128B
#define SM_WY  (32768 + 65536)            // [64 u][256 px] fp16 = 32KB
#define SM_SX  (SM_WY + 32768)            // 256 f32
#define SM_SY  (SM_SX + 1024)             // 256 f32
#define SM_TOT (SM_SY + 1024)             // 133120 B

__device__ __half g_fp16[8 * 8 * 256 * 64];   // 2MB fp16 scratch

__device__ __forceinline__ uint32_t s32(const void* p) {
    uint32_t a;
    asm("{ .reg .u64 t; cvta.to.shared.u64 t, %1; cvt.u32.u64 %0, t; }" : "=r"(a) : "l"(p));
    return a;
}

#define CPA16(dst, src) \
    asm volatile("cp.async.ca.shared.global [%0], [%1], 16;" :: "r"(dst), "l"(src) : "memory")
#define CPA_COMMIT() asm volatile("cp.async.commit_group;" ::: "memory")
#define CPA_WAIT0()  asm volatile("cp.async.wait_group 0;" ::: "memory")

#define LDM4(r0, r1, r2, r3, a) \
    asm volatile("ldmatrix.sync.aligned.m8n8.x4.shared.b16 {%0,%1,%2,%3}, [%4];" \
        : "=r"(r0), "=r"(r1), "=r"(r2), "=r"(r3) : "r"(a))

#define MMA16816(d, a0, a1, a2, a3, b0, b1) \
    asm volatile("mma.sync.aligned.m16n8k16.row.col.f32.f16.f16.f32 " \
        "{%0,%1,%2,%3},{%4,%5,%6,%7},{%8,%9},{%0,%1,%2,%3};" \
        : "+f"((d)[0]), "+f"((d)[1]), "+f"((d)[2]), "+f"((d)[3]) \
        : "r"(a0), "r"(a1), "r"(a2), "r"(a3), "r"(b0), "r"(b1))

// ---------------- prepass: fp32 image -> fp16 scratch ----------------
__global__ void prep_kernel(const float* __restrict__ inp) {
    int g = blockIdx.x * 256 + threadIdx.x;      // 16B units
    int q  = g & 7;
    int n  = (g >> 3) & 255;                     // row = u_local*32 + c
    int ch = (g >> 11) & 7;
    int b  = g >> 14;
    int c  = n & 31;
    int u  = ch * 8 + (n >> 5);
    const float* s = inp + ((size_t)(b * 32 + c) * HWP + u * 64 + q * 8);
    float4 f0 = *(const float4*)s;
    float4 f1 = *(const float4*)(s + 4);
    __half2 h0 = __float22half2_rn(make_float2(f0.x, f0.y));
    __half2 h1 = __float22half2_rn(make_float2(f0.z, f0.w));
    __half2 h2 = __float22half2_rn(make_float2(f1.x, f1.y));
    __half2 h3 = __float22half2_rn(make_float2(f1.z, f1.w));
    uint4 st;
    st.x = *(uint32_t*)&h0; st.y = *(uint32_t*)&h1;
    st.z = *(uint32_t*)&h2; st.w = *(uint32_t*)&h3;
    *(uint4*)(g_fp16 + (((size_t)(b * 8 + ch) * 256 + n) * 64 + q * 8)) = st;
}

// ---------------- main kernel ----------------
__global__ __launch_bounds__(512, 1)
void swapv2_mma(const float* __restrict__ exPx, const float* __restrict__ exPy,
                const float* __restrict__ sigx, const float* __restrict__ sigy,
                float* __restrict__ out)
{
    extern __shared__ char smem[];
    const uint32_t sb = s32(smem);
    const int tid  = threadIdx.x;
    const int lane = tid & 31;
    const int wid  = tid >> 5;                  // 0..15: px strip (16 px)
    const int tile = blockIdx.x;                // 0..15 (256 px each)
    const int b    = blockIdx.y;

    // ---- stage chunk 0 ----
    {
        const __half* src = g_fp16 + (size_t)(b * 8 + 0) * 16384;
        #pragma unroll
        for (int j = 0; j < 4; j++) {
            int idx = tid + j * 512;
            int q = idx & 7, n = idx >> 3;
            CPA16(sb + SM_B + SW((uint32_t)n * 128 + q * 16), src + n * 64 + q * 8);
        }
        CPA_COMMIT();
    }

    // ---- build wx (A, fp16 swz) / wy (fp16) / row sums ----
    if (tid < 256) {
        int px = tid;
        int pidx = b * HWP + tile * 256 + px;
        float ex = exPx[pidx];
        float iv = 0.5f / (sigx[pidx] * sigx[pidx]);
        float sumx = 0.f;
        #pragma unroll
        for (int j = 0; j < 8; j++) {
            uint32_t hh[4];
            #pragma unroll
            for (int h = 0; h < 4; h++) {
                float d0 = (float)(j * 8 + h * 2) - ex;
                float d1 = d0 + 1.f;
                __half2 h2 = __float22half2_rn(make_float2(__expf(-d0 * d0 * iv),
                                                           __expf(-d1 * d1 * iv)));
                float2 bk = __half22float2(h2);
                sumx += bk.x + bk.y;
                hh[h] = *(uint32_t*)&h2;
            }
            *(uint4*)(smem + SM_A + SW((uint32_t)px * 128 + j * 16)) =
                make_uint4(hh[0], hh[1], hh[2], hh[3]);
        }
        ((float*)(smem + SM_SX))[px] = sumx;
    } else {
        int px = tid - 256;
        int pidx = b * HWP + tile * 256 + px;
        float ey = exPy[pidx];
        float iv = 0.5f / (sigy[pidx] * sigy[pidx]);
        float sumy = 0.f;
        __half* wyp = (__half*)(smem + SM_WY);
        #pragma unroll 8
        for (int u = 0; u < 64; u++) {
            float d = (float)u - ey;
            __half w = __float2half_rn(__expf(-d * d * iv));
            wyp[u * 256 + px] = w;
            sumy += __half2float(w);
        }
        ((float*)(smem + SM_SY))[px] = sumy;
    }
    __syncthreads();

    // ---- resident A fragments: 1 m-tile x 4 k-steps x 4 regs = 16 regs ----
    uint32_t A[4][4];
    {
        int r8 = lane & 7, hi8 = (lane >> 3) & 1, kb = lane >> 4;
        #pragma unroll
        for (int ks = 0; ks < 4; ks++) {
            uint32_t off = (uint32_t)(wid * 16 + r8 + hi8 * 8) * 128
                         + ks * 32 + kb * 16;
            LDM4(A[ks][0], A[ks][1], A[ks][2], A[ks][3], sb + SM_A + SW(off));
        }
    }

    float acc[16];                  // [nb 0..3][4]
    #pragma unroll
    for (int i = 0; i < 16; i++) acc[i] = 0.f;

    // ---- chunk loop: wait k, stage k+1, compute k ----
    for (int k = 0; k < 8; k++) {
        CPA_WAIT0();
        __syncthreads();
        if (k < 7) {
            const __half* src = g_fp16 + (size_t)(b * 8 + k + 1) * 16384;
            uint32_t bufo = SM_B + ((k + 1) & 1) * 32768;
            #pragma unroll
            for (int j = 0; j < 4; j++) {
                int idx = tid + j * 512;
                int q = idx & 7, n = idx >> 3;
                CPA16(sb + bufo + SW((uint32_t)n * 128 + q * 16), src + n * 64 + q * 8);
            }
            CPA_COMMIT();
        }

        const uint32_t sbB = sb + SM_B + (k & 1) * 32768;
        const __half* wyp = (const __half*)(smem + SM_WY);
        int g4 = lane >> 2;
        #pragma unroll 1
        for (int uu = 0; uu < 8; uu++) {
            // load B fragments for all 4 n8-blocks (32 channels)
            uint32_t bb[4][8];
            #pragma unroll
            for (int nb = 0; nb < 4; nb++) {
                int nrow = uu * 32 + nb * 8 + (lane & 7);
                uint32_t offb = (uint32_t)nrow * 128 + (lane >> 3) * 16;
                LDM4(bb[nb][0], bb[nb][1], bb[nb][2], bb[nb][3], sbB + SW(offb));
                LDM4(bb[nb][4], bb[nb][5], bb[nb][6], bb[nb][7], sbB + SW(offb + 64));
            }

            float S[16];                     // [nb][4] : 4 independent chains
            #pragma unroll
            for (int i = 0; i < 16; i++) S[i] = 0.f;
            #pragma unroll
            for (int ks = 0; ks < 4; ks++)
                #pragma unroll
                for (int nb = 0; nb < 4; nb++)
                    MMA16816(&S[nb * 4], A[ks][0], A[ks][1], A[ks][2], A[ks][3],
                             bb[nb][2 * ks], bb[nb][2 * ks + 1]);

            const __half* wyrow = wyp + (k * 8 + uu) * 256;
            int px0 = wid * 16 + g4;
            float wy0 = __half2float(wyrow[px0]);
            float wy1 = __half2float(wyrow[px0 + 8]);
            #pragma unroll
            for (int nb = 0; nb < 4; nb++) {
                acc[nb * 4 + 0] = fmaf(wy0, S[nb * 4 + 0], acc[nb * 4 + 0]);
                acc[nb * 4 + 1] = fmaf(wy0, S[nb * 4 + 1], acc[nb * 4 + 1]);
                acc[nb * 4 + 2] = fmaf(wy1, S[nb * 4 + 2], acc[nb * 4 + 2]);
                acc[nb * 4 + 3] = fmaf(wy1, S[nb * 4 + 3], acc[nb * 4 + 3]);
            }
        }
    }

    // ---- write out ----
    const float* sxp = (const float*)(smem + SM_SX);
    const float* syp = (const float*)(smem + SM_SY);
    int g4 = lane >> 2, t4 = lane & 3;
    int px0 = wid * 16 + g4;
    int px1 = px0 + 8;
    float iz0 = 1.0f / (sxp[px0] * syp[px0] + 1e-8f);
    float iz1 = 1.0f / (sxp[px1] * syp[px1] + 1e-8f);
    #pragma unroll
    for (int nb = 0; nb < 4; nb++) {
        int c0 = nb * 8 + t4 * 2;
        size_t base = (size_t)(b * 32 + c0) * HWP + tile * 256;
        out[base + px0]       = acc[nb * 4 + 0] * iz0;
        out[base + HWP + px0] = acc[nb * 4 + 1] * iz0;
        out[base + px1]       = acc[nb * 4 + 2] * iz1;
        out[base + HWP + px1] = acc[nb * 4 + 3] * iz1;
    }
}

extern "C" void kernel_launch(void* const* d_in, const int* in_sizes, int n_in,
                              void* d_out, int out_size) {
    (void)in_sizes; (void)n_in; (void)out_size;
    const float* inp  = (const float*)d_in[0];
    const float* exPx = (const float*)d_in[1];
    const float* exPy = (const float*)d_in[2];
    const float* sigx = (const float*)d_in[3];
    const float* sigy = (const float*)d_in[4];
    float* out = (float*)d_out;

    prep_kernel<<<512, 256>>>(inp);
    cudaFuncSetAttribute(swapv2_mma,
                         cudaFuncAttributeMaxDynamicSharedMemorySize, SM_TOT);
    dim3 grid(16, 8);                 // 128 CTAs = one wave
    swapv2_mma<<<grid, 512, SM_TOT>>>(exPx, exPy, sigx, sigy, out);
}

// round 17
// speedup vs baseline: 1.0458x; 1.0458x over previous
#include <cuda_runtime.h>
#include <cuda_fp16.h>
#include <cstdint>
#include <math.h>

// SwapV2 dense via mma.sync.m16n8k16 (fp16 in, f32 acc). B=8, C=32, H=W=64.
// R17: R15 config (warp = 32px x 16ch, B-frags amortized over 2 m-tiles) +
// linear swizzled LDM addressing (uu stride 4096 commutes with SW128) +
// uu unroll-2 (dual B-frag load batches hide LDM latency under MMA chains).

#define HWP 4096
#define SW(o) ((o) ^ (((o) >> 3) & 0x70))

#define SM_A   0
#define SM_B   32768
#define SM_WY  (32768 + 65536)
#define SM_SX  (SM_WY + 32768)
#define SM_SY  (SM_SX + 1024)
#define SM_TOT (SM_SY + 1024)             // 133120 B

__device__ __half g_fp16[8 * 8 * 256 * 64];   // 2MB fp16 scratch

__device__ __forceinline__ uint32_t s32(const void* p) {
    uint32_t a;
    asm("{ .reg .u64 t; cvta.to.shared.u64 t, %1; cvt.u32.u64 %0, t; }" : "=r"(a) : "l"(p));
    return a;
}

#define CPA16(dst, src) \
    asm volatile("cp.async.ca.shared.global [%0], [%1], 16;" :: "r"(dst), "l"(src) : "memory")
#define CPA_COMMIT() asm volatile("cp.async.commit_group;" ::: "memory")
#define CPA_WAIT0()  asm volatile("cp.async.wait_group 0;" ::: "memory")

#define LDM4(r0, r1, r2, r3, a) \
    asm volatile("ldmatrix.sync.aligned.m8n8.x4.shared.b16 {%0,%1,%2,%3}, [%4];" \
        : "=r"(r0), "=r"(r1), "=r"(r2), "=r"(r3) : "r"(a))

#define MMA16816(d, a0, a1, a2, a3, b0, b1) \
    asm volatile("mma.sync.aligned.m16n8k16.row.col.f32.f16.f16.f32 " \
        "{%0,%1,%2,%3},{%4,%5,%6,%7},{%8,%9},{%0,%1,%2,%3};" \
        : "+f"((d)[0]), "+f"((d)[1]), "+f"((d)[2]), "+f"((d)[3]) \
        : "r"(a0), "r"(a1), "r"(a2), "r"(a3), "r"(b0), "r"(b1))

__global__ void prep_kernel(const float* __restrict__ inp) {
    int g = blockIdx.x * 256 + threadIdx.x;
    int q  = g & 7;
    int n  = (g >> 3) & 255;
    int ch = (g >> 11) & 7;
    int b  = g >> 14;
    int c  = n & 31;
    int u  = ch * 8 + (n >> 5);
    const float* s = inp + ((size_t)(b * 32 + c) * HWP + u * 64 + q * 8);
    float4 f0 = *(const float4*)s;
    float4 f1 = *(const float4*)(s + 4);
    __half2 h0 = __float22half2_rn(make_float2(f0.x, f0.y));
    __half2 h1 = __float22half2_rn(make_float2(f0.z, f0.w));
    __half2 h2 = __float22half2_rn(make_float2(f1.x, f1.y));
    __half2 h3 = __float22half2_rn(make_float2(f1.z, f1.w));
    uint4 st;
    st.x = *(uint32_t*)&h0; st.y = *(uint32_t*)&h1;
    st.z = *(uint32_t*)&h2; st.w = *(uint32_t*)&h3;
    *(uint4*)(g_fp16 + (((size_t)(b * 8 + ch) * 256 + n) * 64 + q * 8)) = st;
}

// one u-value: 16 MMAs over [2 nb][2 mt], epilogue with per-mt wy
#define DO_UU(BB, WYROW)                                                   \
    {                                                                      \
        float S[16];                                                       \
        _Pragma("unroll")                                                  \
        for (int i = 0; i < 16; i++) S[i] = 0.f;                           \
        _Pragma("unroll")                                                  \
        for (int ks = 0; ks < 4; ks++)                                     \
            _Pragma("unroll")                                              \
            for (int nb = 0; nb < 2; nb++)                                 \
                _Pragma("unroll")                                          \
                for (int mt = 0; mt < 2; mt++)                             \
                    MMA16816(&S[nb * 8 + mt * 4],                          \
                             A[mt][ks][0], A[mt][ks][1],                   \
                             A[mt][ks][2], A[mt][ks][3],                   \
                             BB[nb][2 * ks], BB[nb][2 * ks + 1]);          \
        _Pragma("unroll")                                                  \
        for (int mt = 0; mt < 2; mt++) {                                   \
            int pxm = pxg + mt * 16;                                       \
            float wy0 = __half2float((WYROW)[pxm]);                        \
            float wy1 = __half2float((WYROW)[pxm + 8]);                    \
            _Pragma("unroll")                                              \
            for (int nb = 0; nb < 2; nb++) {                               \
                float* ac = acc + nb * 8 + mt * 4;                         \
                const float* sp = S + nb * 8 + mt * 4;                     \
                ac[0] = fmaf(wy0, sp[0], ac[0]);                           \
                ac[1] = fmaf(wy0, sp[1], ac[1]);                           \
                ac[2] = fmaf(wy1, sp[2], ac[2]);                           \
                ac[3] = fmaf(wy1, sp[3], ac[3]);                           \
            }                                                              \
        }                                                                  \
    }

__global__ __launch_bounds__(512, 1)
void swapv2_mma(const float* __restrict__ exPx, const float* __restrict__ exPy,
                const float* __restrict__ sigx, const float* __restrict__ sigy,
                float* __restrict__ out)
{
    extern __shared__ char smem[];
    const uint32_t sb = s32(smem);
    const int tid  = threadIdx.x;
    const int lane = tid & 31;
    const int wid  = tid >> 5;
    const int s    = wid >> 1;
    const int cb   = wid & 1;
    const int tile = blockIdx.x;
    const int b    = blockIdx.y;

    {
        const __half* src = g_fp16 + (size_t)(b * 8 + 0) * 16384;
        #pragma unroll
        for (int j = 0; j < 4; j++) {
            int idx = tid + j * 512;
            int q = idx & 7, n = idx >> 3;
            CPA16(sb + SM_B + SW((uint32_t)n * 128 + q * 16), src + n * 64 + q * 8);
        }
        CPA_COMMIT();
    }

    if (tid < 256) {
        int px = tid;
        int pidx = b * HWP + tile * 256 + px;
        float ex = exPx[pidx];
        float iv = 0.5f / (sigx[pidx] * sigx[pidx]);
        float sumx = 0.f;
        #pragma unroll
        for (int j = 0; j < 8; j++) {
            uint32_t hh[4];
            #pragma unroll
            for (int h = 0; h < 4; h++) {
                float d0 = (float)(j * 8 + h * 2) - ex;
                float d1 = d0 + 1.f;
                __half2 h2 = __float22half2_rn(make_float2(__expf(-d0 * d0 * iv),
                                                           __expf(-d1 * d1 * iv)));
                float2 bk = __half22float2(h2);
                sumx += bk.x + bk.y;
                hh[h] = *(uint32_t*)&h2;
            }
            *(uint4*)(smem + SM_A + SW((uint32_t)px * 128 + j * 16)) =
                make_uint4(hh[0], hh[1], hh[2], hh[3]);
        }
        ((float*)(smem + SM_SX))[px] = sumx;
    } else {
        int px = tid - 256;
        int pidx = b * HWP + tile * 256 + px;
        float ey = exPy[pidx];
        float iv = 0.5f / (sigy[pidx] * sigy[pidx]);
        float sumy = 0.f;
        __half* wyp = (__half*)(smem + SM_WY);
        #pragma unroll 8
        for (int u = 0; u < 64; u++) {
            float d = (float)u - ey;
            __half w = __float2half_rn(__expf(-d * d * iv));
            wyp[u * 256 + px] = w;
            sumy += __half2float(w);
        }
        ((float*)(smem + SM_SY))[px] = sumy;
    }
    __syncthreads();

    uint32_t A[2][4][4];
    {
        int r8 = lane & 7, hi8 = (lane >> 3) & 1, kb = lane >> 4;
        #pragma unroll
        for (int mt = 0; mt < 2; mt++)
            #pragma unroll
            for (int ks = 0; ks < 4; ks++) {
                uint32_t off = (uint32_t)(s * 32 + mt * 16 + r8 + hi8 * 8) * 128
                             + ks * 32 + kb * 16;
                LDM4(A[mt][ks][0], A[mt][ks][1], A[mt][ks][2], A[mt][ks][3],
                     sb + SM_A + SW(off));
            }
    }

    float acc[16];
    #pragma unroll
    for (int i = 0; i < 16; i++) acc[i] = 0.f;

    const uint32_t nrow0 = (uint32_t)(cb * 16 + (lane & 7)) * 128 + (lane >> 3) * 16;
    const uint32_t base00 = SW(nrow0);
    const uint32_t base01 = SW(nrow0 + 64);
    const uint32_t base10 = SW(nrow0 + 8 * 128);
    const uint32_t base11 = SW(nrow0 + 8 * 128 + 64);
    const int pxg = s * 32 + (lane >> 2);

    for (int k = 0; k < 8; k++) {
        CPA_WAIT0();
        __syncthreads();
        if (k < 7) {
            const __half* src = g_fp16 + (size_t)(b * 8 + k + 1) * 16384;
            uint32_t bufo = SM_B + ((k + 1) & 1) * 32768;
            #pragma unroll
            for (int j = 0; j < 4; j++) {
                int idx = tid + j * 512;
                int q = idx & 7, n = idx >> 3;
                CPA16(sb + bufo + SW((uint32_t)n * 128 + q * 16), src + n * 64 + q * 8);
            }
            CPA_COMMIT();
        }

        const uint32_t sbB = sb + SM_B + (k & 1) * 32768;
        const __half* wyp = (const __half*)(smem + SM_WY) + (size_t)k * 8 * 256;

        uint32_t a00 = sbB + base00, a01 = sbB + base01;
        uint32_t a10 = sbB + base10, a11 = sbB + base11;

        #pragma unroll 1
        for (int uu = 0; uu < 8; uu += 2) {
            uint32_t bbA[2][8], bbB[2][8];
            LDM4(bbA[0][0], bbA[0][1], bbA[0][2], bbA[0][3], a00);
            LDM4(bbA[0][4], bbA[0][5], bbA[0][6], bbA[0][7], a01);
            LDM4(bbA[1][0], bbA[1][1], bbA[1][2], bbA[1][3], a10);
            LDM4(bbA[1][4], bbA[1][5], bbA[1][6], bbA[1][7], a11);
            LDM4(bbB[0][0], bbB[0][1], bbB[0][2], bbB[0][3], a00 + 4096);
            LDM4(bbB[0][4], bbB[0][5], bbB[0][6], bbB[0][7], a01 + 4096);
            LDM4(bbB[1][0], bbB[1][1], bbB[1][2], bbB[1][3], a10 + 4096);
            LDM4(bbB[1][4], bbB[1][5], bbB[1][6], bbB[1][7], a11 + 4096);
            a00 += 8192; a01 += 8192; a10 += 8192; a11 += 8192;

            DO_UU(bbA, wyp + (uu + 0) * 256);
            DO_UU(bbB, wyp + (uu + 1) * 256);
        }
    }

    const float* sxp = (const float*)(smem + SM_SX);
    const float* syp = (const float*)(smem + SM_SY);
    int g4 = lane >> 2, t4 = lane & 3;
    #pragma unroll
    for (int nb = 0; nb < 2; nb++) {
        int c0 = cb * 16 + nb * 8 + t4 * 2;
        size_t base = (size_t)(b * 32 + c0) * HWP + tile * 256;
        #pragma unroll
        for (int mt = 0; mt < 2; mt++) {
            int px0 = s * 32 + mt * 16 + g4;
            int px1 = px0 + 8;
            float iz0 = 1.0f / (sxp[px0] * syp[px0] + 1e-8f);
            float iz1 = 1.0f / (sxp[px1] * syp[px1] + 1e-8f);
            const float* ac = acc + nb * 8 + mt * 4;
            out[base + px0]       = ac[0] * iz0;
            out[base + HWP + px0] = ac[1] * iz0;
            out[base + px1]       = ac[2] * iz1;
            out[base + HWP + px1] = ac[3] * iz1;
        }
    }
}

extern "C" void kernel_launch(void* const* d_in, const int* in_sizes, int n_in,
                              void* d_out, int out_size) {
    (void)in_sizes; (void)n_in; (void)out_size;
    const float* inp  = (const float*)d_in[0];
    const float* exPx = (const float*)d_in[1];
    const float* exPy = (const float*)d_in[2];
    const float* sigx = (const float*)d_in[3];
    const float* sigy = (const float*)d_in[4];
    float* out = (float*)d_out;

    prep_kernel<<<512, 256>>>(inp);
    cudaFuncSetAttribute(swapv2_mma,
                         cudaFuncAttributeMaxDynamicSharedMemorySize, SM_TOT);
    dim3 grid(16, 8);
    swapv2_mma<<<grid, 512, SM_TOT>>>(exPx, exPy, sigx, sigy, out);
}